// round 1
// baseline (speedup 1.0000x reference)
#include <cuda_runtime.h>
#include <cstdint>

#define BB 4
#define TT 4096
#define DM 1024
#define DH 64

// scratch for projections (allocation-free rule: __device__ globals)
__device__ float g_q[BB * TT * DH];
__device__ float g_k[BB * TT * DH];
__device__ float g_v[BB * TT * DH];

// ---------------------------------------------------------------------------
// QKV projection: out[m, h] = sum_d x[m, d] * W[h, d]
// M = B*T = 16384, N = 64, K = 1024.  BM=64, BN=64, BK=32, 4x4 micro-tile.
// ---------------------------------------------------------------------------
__global__ void __launch_bounds__(256) proj_kernel(
    const float* __restrict__ x,
    const float* __restrict__ Wq,
    const float* __restrict__ Wk,
    const float* __restrict__ Wv)
{
    __shared__ float As[32][68];  // [k][m], padded
    __shared__ float Bs[32][68];  // [k][n], padded

    const float* W;
    float* out;
    if (blockIdx.y == 0)      { W = Wq; out = g_q; }
    else if (blockIdx.y == 1) { W = Wk; out = g_k; }
    else                      { W = Wv; out = g_v; }

    const int m0  = blockIdx.x * 64;
    const int tid = threadIdx.x;
    const int tx  = tid & 15;   // output col group (n)
    const int ty  = tid >> 4;   // output row group (m)

    const int lr = tid >> 3;        // 0..31: load row
    const int lk = (tid & 7) * 4;   // 0..28: load k offset (float4)

    float acc[4][4] = {};

    for (int k0 = 0; k0 < DM; k0 += 32) {
        __syncthreads();
        #pragma unroll
        for (int half = 0; half < 2; half++) {
            const int row = lr + 32 * half;  // 0..63
            float4 a = *(const float4*)(x + (size_t)(m0 + row) * DM + k0 + lk);
            As[lk + 0][row] = a.x; As[lk + 1][row] = a.y;
            As[lk + 2][row] = a.z; As[lk + 3][row] = a.w;
            float4 w = *(const float4*)(W + (size_t)row * DM + k0 + lk);
            Bs[lk + 0][row] = w.x; Bs[lk + 1][row] = w.y;
            Bs[lk + 2][row] = w.z; Bs[lk + 3][row] = w.w;
        }
        __syncthreads();
        #pragma unroll
        for (int kk = 0; kk < 32; kk++) {
            float4 a4 = *(float4*)(&As[kk][4 * ty]);
            float4 b4 = *(float4*)(&Bs[kk][4 * tx]);
            float av[4] = {a4.x, a4.y, a4.z, a4.w};
            float bv[4] = {b4.x, b4.y, b4.z, b4.w};
            #pragma unroll
            for (int r = 0; r < 4; r++)
                #pragma unroll
                for (int c = 0; c < 4; c++)
                    acc[r][c] = fmaf(av[r], bv[c], acc[r][c]);
        }
    }

    #pragma unroll
    for (int r = 0; r < 4; r++) {
        float4 o = make_float4(acc[r][0], acc[r][1], acc[r][2], acc[r][3]);
        *(float4*)(out + (size_t)(m0 + 4 * ty + r) * DH + 4 * tx) = o;
    }
}

// ---------------------------------------------------------------------------
// Flash attention with relative position bias + causal mask.
// Br = Bc = 64, 256 threads (16x16), 4x4 fragments.
// Shared (dynamic): Qs[64][68] (h-major), Ks[64][68] (h-major),
//                   Vs[64][68] (j-major), Ps[64][68] (j-major), sRel[17].
// ---------------------------------------------------------------------------
#define SROW 68
#define SMEM_FLOATS (4 * 64 * SROW + 32)
#define SMEM_BYTES  (SMEM_FLOATS * 4)

__global__ void __launch_bounds__(256) attn_kernel(
    const float* __restrict__ rel_emb,
    float* __restrict__ out)
{
    extern __shared__ float sm[];
    float* Qs   = sm;
    float* Ks   = sm + 64 * SROW;
    float* Vs   = sm + 2 * 64 * SROW;
    float* Ps   = sm + 3 * 64 * SROW;
    float* sRel = sm + 4 * 64 * SROW;

    const int tid = threadIdx.x;
    const int tx  = tid & 15;
    const int ty  = tid >> 4;
    const int rt  = blockIdx.x;    // row tile 0..63
    const int b   = blockIdx.y;
    const int i0  = rt * 64;

    if (tid < 17) sRel[tid] = rel_emb[tid];

    // load Q tile transposed: Qs[h][i]
    {
        const int i  = tid >> 2;
        const int hb = (tid & 3) * 4;
        const float* qp = g_q + (size_t)(b * TT + i0 + i) * DH;
        #pragma unroll
        for (int q = 0; q < 4; q++) {
            const int h = hb + 16 * q;
            float4 v = *(const float4*)(qp + h);
            Qs[(h + 0) * SROW + i] = v.x;
            Qs[(h + 1) * SROW + i] = v.y;
            Qs[(h + 2) * SROW + i] = v.z;
            Qs[(h + 3) * SROW + i] = v.w;
        }
    }

    float o[4][4] = {};
    float m[4], l[4];
    #pragma unroll
    for (int r = 0; r < 4; r++) { m[r] = -1e30f; l[r] = 0.f; }

    for (int ct = 0; ct <= rt; ct++) {
        const int j0 = ct * 64;
        __syncthreads();   // prev PV done, Q/sRel visible
        // load K transposed (Ks[h][j]) and V natural (Vs[j][d])
        {
            const int j  = tid >> 2;
            const int hb = (tid & 3) * 4;
            const float* kp = g_k + (size_t)(b * TT + j0 + j) * DH;
            const float* vp = g_v + (size_t)(b * TT + j0 + j) * DH;
            #pragma unroll
            for (int q = 0; q < 4; q++) {
                const int h = hb + 16 * q;
                float4 kv = *(const float4*)(kp + h);
                Ks[(h + 0) * SROW + j] = kv.x;
                Ks[(h + 1) * SROW + j] = kv.y;
                Ks[(h + 2) * SROW + j] = kv.z;
                Ks[(h + 3) * SROW + j] = kv.w;
                float4 vv = *(const float4*)(vp + h);
                *(float4*)(&Vs[j * SROW + h]) = vv;
            }
        }
        __syncthreads();

        // S = Q K^T
        float s[4][4] = {};
        #pragma unroll 16
        for (int kk = 0; kk < 64; kk++) {
            float4 a4 = *(float4*)(&Qs[kk * SROW + 4 * ty]);
            float4 b4 = *(float4*)(&Ks[kk * SROW + 4 * tx]);
            float av[4] = {a4.x, a4.y, a4.z, a4.w};
            float bv[4] = {b4.x, b4.y, b4.z, b4.w};
            #pragma unroll
            for (int r = 0; r < 4; r++)
                #pragma unroll
                for (int c = 0; c < 4; c++)
                    s[r][c] = fmaf(av[r], bv[c], s[r][c]);
        }

        // scale + rel bias + causal mask
        const float b0 = sRel[0];
        if (ct + 1 < rt) {
            // far tile: j - i <= -65 always -> bias saturates at rel_emb[0]; no mask
            #pragma unroll
            for (int r = 0; r < 4; r++)
                #pragma unroll
                for (int c = 0; c < 4; c++)
                    s[r][c] = s[r][c] * 0.125f + b0;
        } else {
            #pragma unroll
            for (int r = 0; r < 4; r++)
                #pragma unroll
                for (int c = 0; c < 4; c++) {
                    const int d = (j0 + 4 * tx + c) - (i0 + 4 * ty + r);
                    if (d > 0) s[r][c] = -1e30f;
                    else       s[r][c] = s[r][c] * 0.125f + sRel[(d < -8 ? -8 : d) + 8];
                }
        }

        // online softmax update
        #pragma unroll
        for (int r = 0; r < 4; r++) {
            float tm = fmaxf(fmaxf(s[r][0], s[r][1]), fmaxf(s[r][2], s[r][3]));
            tm = fmaxf(tm, __shfl_xor_sync(0xffffffffu, tm, 1));
            tm = fmaxf(tm, __shfl_xor_sync(0xffffffffu, tm, 2));
            tm = fmaxf(tm, __shfl_xor_sync(0xffffffffu, tm, 4));
            tm = fmaxf(tm, __shfl_xor_sync(0xffffffffu, tm, 8));
            const float mn  = fmaxf(m[r], tm);
            const float fac = __expf(m[r] - mn);
            m[r] = mn;
            float rs = 0.f;
            #pragma unroll
            for (int c = 0; c < 4; c++) {
                const float p = __expf(s[r][c] - mn);
                s[r][c] = p;
                rs += p;
            }
            rs += __shfl_xor_sync(0xffffffffu, rs, 1);
            rs += __shfl_xor_sync(0xffffffffu, rs, 2);
            rs += __shfl_xor_sync(0xffffffffu, rs, 4);
            rs += __shfl_xor_sync(0xffffffffu, rs, 8);
            l[r] = l[r] * fac + rs;
            #pragma unroll
            for (int c = 0; c < 4; c++) o[r][c] *= fac;
        }

        // stage P transposed: Ps[j][i]
        #pragma unroll
        for (int c = 0; c < 4; c++) {
            float4 pv = make_float4(s[0][c], s[1][c], s[2][c], s[3][c]);
            *(float4*)(&Ps[(4 * tx + c) * SROW + 4 * ty]) = pv;
        }
        __syncthreads();

        // O += P V
        #pragma unroll 16
        for (int jj = 0; jj < 64; jj++) {
            float4 a4 = *(float4*)(&Ps[jj * SROW + 4 * ty]);
            float4 b4 = *(float4*)(&Vs[jj * SROW + 4 * tx]);
            float av[4] = {a4.x, a4.y, a4.z, a4.w};
            float bv[4] = {b4.x, b4.y, b4.z, b4.w};
            #pragma unroll
            for (int r = 0; r < 4; r++)
                #pragma unroll
                for (int c = 0; c < 4; c++)
                    o[r][c] = fmaf(av[r], bv[c], o[r][c]);
        }
    }

    // epilogue: normalize and store
    #pragma unroll
    for (int r = 0; r < 4; r++) {
        const float inv = 1.0f / l[r];
        float4 ov = make_float4(o[r][0] * inv, o[r][1] * inv,
                                o[r][2] * inv, o[r][3] * inv);
        *(float4*)(out + (size_t)(b * TT + i0 + 4 * ty + r) * DH + 4 * tx) = ov;
    }
}

extern "C" void kernel_launch(void* const* d_in, const int* in_sizes, int n_in,
                              void* d_out, int out_size)
{
    const float* x   = (const float*)d_in[0];
    const float* Wq  = (const float*)d_in[1];
    const float* Wk  = (const float*)d_in[2];
    const float* Wv  = (const float*)d_in[3];
    const float* rel = (const float*)d_in[4];
    float* out = (float*)d_out;

    dim3 pgrid(BB * TT / 64, 3);
    proj_kernel<<<pgrid, 256>>>(x, Wq, Wk, Wv);

    cudaFuncSetAttribute(attn_kernel,
                         cudaFuncAttributeMaxDynamicSharedMemorySize, SMEM_BYTES);
    dim3 agrid(TT / 64, BB);
    attn_kernel<<<agrid, 256, SMEM_BYTES>>>(rel, out);
}

// round 2
// speedup vs baseline: 1.5191x; 1.5191x over previous
#include <cuda_runtime.h>
#include <cstdint>

#define BB 4
#define TT 4096
#define DM 1024
#define DH 64
#define CHT 8   // KV tiles (of 64) per attention work unit

// scratch (allocation-free rule: __device__ globals)
__device__ float g_q[BB * TT * DH];
__device__ float g_k[BB * TT * DH];
__device__ float g_v[BB * TT * DH];
// split-KV partials: [b][rt][chunk][i(64)][h(64)], m/l: [b][rt][chunk][i]
__device__ float g_po[BB * 64 * 8 * 64 * 64];
__device__ float g_pm[BB * 64 * 8 * 64];
__device__ float g_pl[BB * 64 * 8 * 64];

// ---------------------------------------------------------------------------
// QKV projection: out[m, h] = sum_d x[m, d] * W[h, d]
// M = 16384, N = 64, K = 1024. BM=128, BN=64, BK=32, 8x8 micro, 128 threads.
// ---------------------------------------------------------------------------
__global__ void __launch_bounds__(128) proj_kernel(
    const float* __restrict__ x,
    const float* __restrict__ Wq,
    const float* __restrict__ Wk,
    const float* __restrict__ Wv)
{
    __shared__ float As[32][132];  // [k][m]
    __shared__ float Bs[32][68];   // [k][n]

    const float* W;
    float* out;
    if (blockIdx.y == 0)      { W = Wq; out = g_q; }
    else if (blockIdx.y == 1) { W = Wk; out = g_k; }
    else                      { W = Wv; out = g_v; }

    const int m0  = blockIdx.x * 128;
    const int tid = threadIdx.x;
    const int tx  = tid & 7;    // col group (8 cols)
    const int ty  = tid >> 3;   // row group (8 rows)

    float acc[8][8] = {};

    for (int k0 = 0; k0 < DM; k0 += 32) {
        __syncthreads();
        #pragma unroll
        for (int it = 0; it < 8; it++) {          // A: 128x32 = 1024 float4
            const int idx = tid + 128 * it;
            const int row = idx >> 3;
            const int c4  = (idx & 7) * 4;
            float4 a = *(const float4*)(x + (size_t)(m0 + row) * DM + k0 + c4);
            As[c4 + 0][row] = a.x; As[c4 + 1][row] = a.y;
            As[c4 + 2][row] = a.z; As[c4 + 3][row] = a.w;
        }
        #pragma unroll
        for (int it = 0; it < 4; it++) {          // B: 64x32 = 512 float4
            const int idx = tid + 128 * it;
            const int row = idx >> 3;
            const int c4  = (idx & 7) * 4;
            float4 w = *(const float4*)(W + (size_t)row * DM + k0 + c4);
            Bs[c4 + 0][row] = w.x; Bs[c4 + 1][row] = w.y;
            Bs[c4 + 2][row] = w.z; Bs[c4 + 3][row] = w.w;
        }
        __syncthreads();
        #pragma unroll
        for (int kk = 0; kk < 32; kk++) {
            float4 a0 = *(float4*)(&As[kk][8 * ty]);
            float4 a1 = *(float4*)(&As[kk][8 * ty + 4]);
            float4 b0 = *(float4*)(&Bs[kk][8 * tx]);
            float4 b1 = *(float4*)(&Bs[kk][8 * tx + 4]);
            float av[8] = {a0.x, a0.y, a0.z, a0.w, a1.x, a1.y, a1.z, a1.w};
            float bv[8] = {b0.x, b0.y, b0.z, b0.w, b1.x, b1.y, b1.z, b1.w};
            #pragma unroll
            for (int r = 0; r < 8; r++)
                #pragma unroll
                for (int c = 0; c < 8; c++)
                    acc[r][c] = fmaf(av[r], bv[c], acc[r][c]);
        }
    }

    #pragma unroll
    for (int r = 0; r < 8; r++) {
        float* op = out + (size_t)(m0 + 8 * ty + r) * DH + 8 * tx;
        *(float4*)(op)     = make_float4(acc[r][0], acc[r][1], acc[r][2], acc[r][3]);
        *(float4*)(op + 4) = make_float4(acc[r][4], acc[r][5], acc[r][6], acc[r][7]);
    }
}

// ---------------------------------------------------------------------------
// Split-KV flash attention partial: block = (rt, chunk, b).
// Processes KV tiles ct in [chunk*CHT, min(rt, chunk*CHT+CHT-1)].
// Writes unnormalized O + (m, l) to scratch.
// ---------------------------------------------------------------------------
#define SROW 68
#define SMEM_FLOATS (4 * 64 * SROW + 32)
#define SMEM_BYTES  (SMEM_FLOATS * 4)

__global__ void __launch_bounds__(256) attn_part_kernel(
    const float* __restrict__ rel_emb)
{
    const int rt    = blockIdx.x;
    const int chunk = blockIdx.y;
    const int b     = blockIdx.z;
    const int ct0   = chunk * CHT;
    if (ct0 > rt) return;
    const int ct1 = min(rt, ct0 + CHT - 1);

    extern __shared__ float sm[];
    float* Qs   = sm;
    float* Ks   = sm + 64 * SROW;
    float* Vs   = sm + 2 * 64 * SROW;
    float* Ps   = sm + 3 * 64 * SROW;
    float* sRel = sm + 4 * 64 * SROW;

    const int tid = threadIdx.x;
    const int tx  = tid & 15;
    const int ty  = tid >> 4;
    const int i0  = rt * 64;

    if (tid < 17) sRel[tid] = rel_emb[tid];

    // load Q tile transposed: Qs[h][i]
    {
        const int i  = tid >> 2;
        const int hb = (tid & 3) * 4;
        const float* qp = g_q + (size_t)(b * TT + i0 + i) * DH;
        #pragma unroll
        for (int q = 0; q < 4; q++) {
            const int h = hb + 16 * q;
            float4 v = *(const float4*)(qp + h);
            Qs[(h + 0) * SROW + i] = v.x;
            Qs[(h + 1) * SROW + i] = v.y;
            Qs[(h + 2) * SROW + i] = v.z;
            Qs[(h + 3) * SROW + i] = v.w;
        }
    }

    float o[4][4] = {};
    float m[4], l[4];
    #pragma unroll
    for (int r = 0; r < 4; r++) { m[r] = -1e30f; l[r] = 0.f; }

    for (int ct = ct0; ct <= ct1; ct++) {
        const int j0 = ct * 64;
        __syncthreads();   // prev PV done, Q/sRel visible
        {
            const int j  = tid >> 2;
            const int hb = (tid & 3) * 4;
            const float* kp = g_k + (size_t)(b * TT + j0 + j) * DH;
            const float* vp = g_v + (size_t)(b * TT + j0 + j) * DH;
            #pragma unroll
            for (int q = 0; q < 4; q++) {
                const int h = hb + 16 * q;
                float4 kv = *(const float4*)(kp + h);
                Ks[(h + 0) * SROW + j] = kv.x;
                Ks[(h + 1) * SROW + j] = kv.y;
                Ks[(h + 2) * SROW + j] = kv.z;
                Ks[(h + 3) * SROW + j] = kv.w;
                float4 vv = *(const float4*)(vp + h);
                *(float4*)(&Vs[j * SROW + h]) = vv;
            }
        }
        __syncthreads();

        // S = Q K^T
        float s[4][4] = {};
        #pragma unroll 16
        for (int kk = 0; kk < 64; kk++) {
            float4 a4 = *(float4*)(&Qs[kk * SROW + 4 * ty]);
            float4 b4 = *(float4*)(&Ks[kk * SROW + 4 * tx]);
            float av[4] = {a4.x, a4.y, a4.z, a4.w};
            float bv[4] = {b4.x, b4.y, b4.z, b4.w};
            #pragma unroll
            for (int r = 0; r < 4; r++)
                #pragma unroll
                for (int c = 0; c < 4; c++)
                    s[r][c] = fmaf(av[r], bv[c], s[r][c]);
        }

        // scale + rel bias + causal mask
        const float b0 = sRel[0];
        if (ct + 1 < rt) {
            #pragma unroll
            for (int r = 0; r < 4; r++)
                #pragma unroll
                for (int c = 0; c < 4; c++)
                    s[r][c] = s[r][c] * 0.125f + b0;
        } else {
            #pragma unroll
            for (int r = 0; r < 4; r++)
                #pragma unroll
                for (int c = 0; c < 4; c++) {
                    const int d = (j0 + 4 * tx + c) - (i0 + 4 * ty + r);
                    if (d > 0) s[r][c] = -1e30f;
                    else       s[r][c] = s[r][c] * 0.125f + sRel[(d < -8 ? -8 : d) + 8];
                }
        }

        // online softmax update
        #pragma unroll
        for (int r = 0; r < 4; r++) {
            float tm = fmaxf(fmaxf(s[r][0], s[r][1]), fmaxf(s[r][2], s[r][3]));
            tm = fmaxf(tm, __shfl_xor_sync(0xffffffffu, tm, 1));
            tm = fmaxf(tm, __shfl_xor_sync(0xffffffffu, tm, 2));
            tm = fmaxf(tm, __shfl_xor_sync(0xffffffffu, tm, 4));
            tm = fmaxf(tm, __shfl_xor_sync(0xffffffffu, tm, 8));
            const float mn  = fmaxf(m[r], tm);
            const float fac = __expf(m[r] - mn);
            m[r] = mn;
            float rs = 0.f;
            #pragma unroll
            for (int c = 0; c < 4; c++) {
                const float p = __expf(s[r][c] - mn);
                s[r][c] = p;
                rs += p;
            }
            rs += __shfl_xor_sync(0xffffffffu, rs, 1);
            rs += __shfl_xor_sync(0xffffffffu, rs, 2);
            rs += __shfl_xor_sync(0xffffffffu, rs, 4);
            rs += __shfl_xor_sync(0xffffffffu, rs, 8);
            l[r] = l[r] * fac + rs;
            #pragma unroll
            for (int c = 0; c < 4; c++) o[r][c] *= fac;
        }

        // stage P transposed: Ps[j][i]
        #pragma unroll
        for (int c = 0; c < 4; c++) {
            float4 pv = make_float4(s[0][c], s[1][c], s[2][c], s[3][c]);
            *(float4*)(&Ps[(4 * tx + c) * SROW + 4 * ty]) = pv;
        }
        __syncthreads();

        // O += P V
        #pragma unroll 16
        for (int jj = 0; jj < 64; jj++) {
            float4 a4 = *(float4*)(&Ps[jj * SROW + 4 * ty]);
            float4 b4 = *(float4*)(&Vs[jj * SROW + 4 * tx]);
            float av[4] = {a4.x, a4.y, a4.z, a4.w};
            float bv[4] = {b4.x, b4.y, b4.z, b4.w};
            #pragma unroll
            for (int r = 0; r < 4; r++)
                #pragma unroll
                for (int c = 0; c < 4; c++)
                    o[r][c] = fmaf(av[r], bv[c], o[r][c]);
        }
    }

    // write partials (unnormalized O, m, l)
    const size_t unit = ((size_t)(b * 64 + rt) * 8 + chunk);
    float* po = g_po + unit * 64 * 64;
    #pragma unroll
    for (int r = 0; r < 4; r++) {
        *(float4*)(po + (size_t)(4 * ty + r) * 64 + 4 * tx) =
            make_float4(o[r][0], o[r][1], o[r][2], o[r][3]);
        if (tx == 0) {
            g_pm[unit * 64 + 4 * ty + r] = m[r];
            g_pl[unit * 64 + 4 * ty + r] = l[r];
        }
    }
}

// ---------------------------------------------------------------------------
// Combine partials: out = sum_p exp(m_p - M) * O_p / L
// ---------------------------------------------------------------------------
__global__ void __launch_bounds__(256) combine_kernel(float* __restrict__ out)
{
    const int rt  = blockIdx.x;
    const int b   = blockIdx.y;
    const int nch = rt / CHT + 1;
    const size_t base = ((size_t)(b * 64 + rt) * 8);

    __shared__ float sF[8][64];
    __shared__ float sInvL[64];

    const int tid = threadIdx.x;
    if (tid < 64) {
        float M = -1e30f;
        for (int p = 0; p < nch; p++)
            M = fmaxf(M, g_pm[(base + p) * 64 + tid]);
        float L = 0.f;
        for (int p = 0; p < nch; p++) {
            const float f = __expf(g_pm[(base + p) * 64 + tid] - M);
            sF[p][tid] = f;
            L += g_pl[(base + p) * 64 + tid] * f;
        }
        sInvL[tid] = 1.0f / L;
    }
    __syncthreads();

    const int r  = tid >> 2;
    const int h0 = (tid & 3) * 16;
    float acc[16] = {};
    for (int p = 0; p < nch; p++) {
        const float f = sF[p][r];
        const float* po = g_po + ((base + p) * 64 + r) * 64 + h0;
        #pragma unroll
        for (int u = 0; u < 16; u += 4) {
            float4 v = *(const float4*)(po + u);
            acc[u + 0] = fmaf(f, v.x, acc[u + 0]);
            acc[u + 1] = fmaf(f, v.y, acc[u + 1]);
            acc[u + 2] = fmaf(f, v.z, acc[u + 2]);
            acc[u + 3] = fmaf(f, v.w, acc[u + 3]);
        }
    }
    const float inv = sInvL[r];
    float* op = out + (size_t)(b * TT + rt * 64 + r) * DH + h0;
    #pragma unroll
    for (int u = 0; u < 16; u += 4)
        *(float4*)(op + u) = make_float4(acc[u] * inv, acc[u + 1] * inv,
                                         acc[u + 2] * inv, acc[u + 3] * inv);
}

extern "C" void kernel_launch(void* const* d_in, const int* in_sizes, int n_in,
                              void* d_out, int out_size)
{
    const float* x   = (const float*)d_in[0];
    const float* Wq  = (const float*)d_in[1];
    const float* Wk  = (const float*)d_in[2];
    const float* Wv  = (const float*)d_in[3];
    const float* rel = (const float*)d_in[4];
    float* out = (float*)d_out;

    dim3 pgrid(BB * TT / 128, 3);
    proj_kernel<<<pgrid, 128>>>(x, Wq, Wk, Wv);

    cudaFuncSetAttribute(attn_part_kernel,
                         cudaFuncAttributeMaxDynamicSharedMemorySize, SMEM_BYTES);
    dim3 agrid(TT / 64, 8, BB);
    attn_part_kernel<<<agrid, 256, SMEM_BYTES>>>(rel);

    dim3 cgrid(TT / 64, BB);
    combine_kernel<<<cgrid, 256>>>(out);
}